// round 4
// baseline (speedup 1.0000x reference)
#include <cuda_runtime.h>
#include <stdint.h>

#define C 1280
#define NIMG 8192          // B*K = 2048*4
#define NPAT 2048
#define PAIRS 6
#define PC 15728640u       // 12288 * 1280  (mask plane stride per dropout)

#define BM 128
#define BN 64
#define BK 16

// Scratch for the per-image conv outputs (ch0 and ch1 planes).
__device__ float g_Y0[NIMG * C];
__device__ float g_Y1[NIMG * C];

// ---------------- packed f32x2 helpers ----------------
__device__ __forceinline__ unsigned long long pack2(float x, float y) {
    unsigned long long r;
    asm("mov.b64 %0, {%1, %2};" : "=l"(r) : "f"(x), "f"(y));
    return r;
}
__device__ __forceinline__ float2 unpack2(unsigned long long v) {
    float2 r;
    asm("mov.b64 {%0, %1}, %2;" : "=f"(r.x), "=f"(r.y) : "l"(v));
    return r;
}
__device__ __forceinline__ void ffma2(unsigned long long& d, unsigned long long a,
                                      unsigned long long b) {
    asm("fma.rn.f32x2 %0, %1, %2, %0;" : "+l"(d) : "l"(a), "l"(b));
}

// ---------------- Kernel A: Y0/Y1 = X @ Wc[:,:,0/1]^T ----------------
// X: [8192,1280] row-major. W (float2): W[o*1280+i] = (Wc[o,i,0], Wc[o,i,1]).
__global__ __launch_bounds__(256, 2)
void conv_gemm_kernel(const float* __restrict__ X, const float2* __restrict__ W) {
    __shared__ float  As[BK][BM];
    __shared__ float2 Bs[BK][BN + 1];   // +1 float2 pad: conflict-free stores

    const int tid = threadIdx.x;
    const int bm  = blockIdx.y * BM;
    const int bn  = blockIdx.x * BN;
    const int tm  = (tid >> 4) * 8;     // 8 M-rows, contiguous
    const int tn  = (tid & 15);         // 4 N-cols, stride 16 (coalesced epilogue)

    unsigned long long acc[8][4];
#pragma unroll
    for (int i = 0; i < 8; i++)
#pragma unroll
        for (int j = 0; j < 4; j++) acc[i][j] = 0ull;

    const int lr = tid >> 2;            // 0..63
    const int lk = (tid & 3) * 4;       // 0,4,8,12

    for (int k0 = 0; k0 < C; k0 += BK) {
        float4 a0 = *(const float4*)(X + (size_t)(bm + lr)      * C + k0 + lk);
        float4 a1 = *(const float4*)(X + (size_t)(bm + lr + 64) * C + k0 + lk);
        const float4* bsrc = (const float4*)(W + (size_t)(bn + lr) * C + k0 + lk);
        float4 w01 = bsrc[0];
        float4 w23 = bsrc[1];

        As[lk + 0][lr] = a0.x; As[lk + 1][lr] = a0.y;
        As[lk + 2][lr] = a0.z; As[lk + 3][lr] = a0.w;
        As[lk + 0][lr + 64] = a1.x; As[lk + 1][lr + 64] = a1.y;
        As[lk + 2][lr + 64] = a1.z; As[lk + 3][lr + 64] = a1.w;
        Bs[lk + 0][lr] = make_float2(w01.x, w01.y);
        Bs[lk + 1][lr] = make_float2(w01.z, w01.w);
        Bs[lk + 2][lr] = make_float2(w23.x, w23.y);
        Bs[lk + 3][lr] = make_float2(w23.z, w23.w);
        __syncthreads();

#pragma unroll
        for (int k = 0; k < BK; k++) {
            const float4* arow = (const float4*)&As[k][tm];
            float4 af0 = arow[0], af1 = arow[1];
            float a[8] = {af0.x, af0.y, af0.z, af0.w, af1.x, af1.y, af1.z, af1.w};
            unsigned long long bw[4];
#pragma unroll
            for (int j = 0; j < 4; j++)
                bw[j] = *(const unsigned long long*)&Bs[k][tn + 16 * j];
#pragma unroll
            for (int i = 0; i < 8; i++) {
                unsigned long long a2 = pack2(a[i], a[i]);
#pragma unroll
                for (int j = 0; j < 4; j++) ffma2(acc[i][j], a2, bw[j]);
            }
        }
        __syncthreads();
    }

#pragma unroll
    for (int i = 0; i < 8; i++) {
        const int row = bm + tm + i;
#pragma unroll
        for (int j = 0; j < 4; j++) {
            float2 v = unpack2(acc[i][j]);
            const int col = bn + tn + 16 * j;
            g_Y0[(size_t)row * C + col] = v.x;
            g_Y1[(size_t)row * C + col] = v.y;
        }
    }
}

// ---------------- Threefry-2x32, JAX *partitionable* stream ----------------
// Element flat index i (< 2^32): counter = (hi=0, lo=i), key = (0, 42).
// 32-bit draw = bits1 ^ bits2 (XOR fold of the two output words).
// keep (u < 0.5)  <=>  MSB of draw == 0.
__device__ __forceinline__ uint32_t rotl32(uint32_t x, int r) {
    return __funnelshift_l(x, x, r);
}

// Returns n1 = number of keep-bits across the 5 dropout planes for flat
// offset base = p*1280 + c (plane stride PC). 5 chains interleaved for ILP.
__device__ __forceinline__ int tf_n1(uint32_t base) {
    const uint32_t ks0 = 0u, ks1 = 42u, ks2 = 0x1BD11BF0u;  // 0x1BD11BDA ^ 0 ^ 42
    uint32_t x0[5], x1[5];
#pragma unroll
    for (int d = 0; d < 5; d++) {
        x0[d] = ks0;                              // counter-hi (0) + ks0
        x1[d] = base + (uint32_t)d * PC + ks1;    // counter-lo + ks1
    }

#define TF_ROUND(r)                                           \
    {                                                         \
        _Pragma("unroll") for (int e = 0; e < 5; e++) {       \
            x0[e] += x1[e];                                   \
            x1[e] = rotl32(x1[e], (r));                       \
            x1[e] ^= x0[e];                                   \
        }                                                     \
    }
#define TF_INJ(a, b)                                          \
    {                                                         \
        _Pragma("unroll") for (int e = 0; e < 5; e++) {       \
            x0[e] += (a); x1[e] += (b);                       \
        }                                                     \
    }
    TF_ROUND(13) TF_ROUND(15) TF_ROUND(26) TF_ROUND(6)  TF_INJ(ks1, ks2 + 1u)
    TF_ROUND(17) TF_ROUND(29) TF_ROUND(16) TF_ROUND(24) TF_INJ(ks2, ks0 + 2u)
    TF_ROUND(13) TF_ROUND(15) TF_ROUND(26) TF_ROUND(6)  TF_INJ(ks0, ks1 + 3u)
    TF_ROUND(17) TF_ROUND(29) TF_ROUND(16) TF_ROUND(24) TF_INJ(ks1, ks2 + 4u)
    TF_ROUND(13) TF_ROUND(15) TF_ROUND(26) TF_ROUND(6)  TF_INJ(ks2, ks0 + 5u)
#undef TF_ROUND
#undef TF_INJ

    int msum = 0;
#pragma unroll
    for (int d = 0; d < 5; d++) msum += (int)((x0[d] ^ x1[d]) >> 31);
    return 5 - msum;
}

// ---------------- Kernel B: relu + mask-count + 3 heads + segment mean ----
// One block per patient (2048 blocks).
__global__ __launch_bounds__(256, 4)
void reduce_kernel(const float* __restrict__ bc,
                   const float* __restrict__ W0, const float* __restrict__ b0,
                   const float* __restrict__ W1, const float* __restrict__ b1,
                   const float* __restrict__ W2, const float* __restrict__ b2,
                   float* __restrict__ out) {
    __shared__ float sW0[C], sW1[C], sW2[C], sbc[C];
    __shared__ float red[24];

    const int tid = threadIdx.x;
    for (int i = tid; i < C; i += 256) {
        sW0[i] = W0[i]; sW1[i] = W1[i]; sW2[i] = W2[i]; sbc[i] = bc[i];
    }
    __syncthreads();

    const int b = blockIdx.x;       // 0..2047

    float a0 = 0.f, a1 = 0.f, a2 = 0.f;

#pragma unroll
    for (int j = 0; j < PAIRS; j++) {
        const int ii = (j < 3) ? 0 : ((j < 5) ? 1 : 2);
        const int jj = (j < 3) ? (j + 1) : ((j < 5) ? (j - 1) : 3);
        const float* y0 = g_Y0 + (size_t)(4 * b + ii) * C;
        const float* y1 = g_Y1 + (size_t)(4 * b + jj) * C;
        const uint32_t p = (uint32_t)(PAIRS * b + j);

        for (int c = tid; c < C; c += 256) {
            float xc = fmaxf(y0[c] + y1[c] + sbc[c], 0.f);
            const int n1 = tf_n1(p * 1280u + (uint32_t)c);
            float t = xc * (float)n1;
            a0 = fmaf(t, sW0[c], a0);
            a1 = fmaf(t, sW1[c], a1);
            a2 = fmaf(t, sW2[c], a2);
        }
    }

    // block reduction of 3 scalars (deterministic)
    float vals[3] = {a0, a1, a2};
    const int lane = tid & 31, wid = tid >> 5;
#pragma unroll
    for (int v = 0; v < 3; v++) {
        float s = vals[v];
#pragma unroll
        for (int off = 16; off; off >>= 1) s += __shfl_down_sync(0xffffffffu, s, off);
        if (lane == 0) red[v * 8 + wid] = s;
    }
    __syncthreads();
    if (tid < 3) {
        float s = 0.f;
#pragma unroll
        for (int w = 0; w < 8; w++) s += red[tid * 8 + w];
        const float* bias = (tid == 0) ? b0 : ((tid == 1) ? b1 : b2);
        // logit = bias + (2 / (5 dropouts * 6 pairs)) * S = bias + S/15
        out[b * 3 + tid] = bias[0] + s * (1.0f / 15.0f);
    }
}

extern "C" void kernel_launch(void* const* d_in, const int* in_sizes, int n_in,
                              void* d_out, int out_size) {
    (void)in_sizes; (void)n_in; (void)out_size;
    const float*  x  = (const float*) d_in[0];
    // d_in[1] = ids2 (structure is static: repeat(arange(2048), 6)) — unused
    const float2* Wc = (const float2*)d_in[2];   // (C,C,2) -> float2 pairs
    const float*  bc = (const float*) d_in[3];
    const float*  W0 = (const float*) d_in[4];
    const float*  b0 = (const float*) d_in[5];
    const float*  W1 = (const float*) d_in[6];
    const float*  b1 = (const float*) d_in[7];
    const float*  W2 = (const float*) d_in[8];
    const float*  b2 = (const float*) d_in[9];
    float* out = (float*)d_out;

    dim3 gridA(C / BN, NIMG / BM);   // (20, 64)
    conv_gemm_kernel<<<gridA, 256>>>(x, Wc);
    reduce_kernel<<<NPAT, 256>>>(bc, W0, b0, W1, b1, W2, b2, out);
}

// round 10
// speedup vs baseline: 1.9081x; 1.9081x over previous
#include <cuda_runtime.h>
#include <cuda_bf16.h>
#include <stdint.h>

#define C 1280
#define NIMG 8192          // B*K = 2048*4
#define NPAT 2048
#define PAIRS 6
#define PC 15728640u       // 12288 * 1280  (mask plane stride per dropout)

// ---- GEMM tiling: CTA 128x128, 8 warps (2 M x 4 N), warp 64x32 ----
#define TMt 128
#define TNt 128
#define KCH 32             // bf16 K elems per chunk = 64 B/row
#define NCHUNK 120         // 3 planes * (1280/32)
#define NSTAGE 4
#define STAGE_BYTES 16384  // A 8KB + B 8KB
#define DYN_SMEM (NSTAGE * STAGE_BYTES)

// Scratch — 256B-aligned: cp.async needs 16B, float2 stores need 8B.
__device__ __align__(256) float g_Y0[NIMG * C];
__device__ __align__(256) float g_Y1[NIMG * C];
__device__ __align__(256) __nv_bfloat16 g_Xhi[NIMG * C];
__device__ __align__(256) __nv_bfloat16 g_Xlo[NIMG * C];
__device__ __align__(256) __nv_bfloat16 g_Bhi[2 * C * C];  // 0..1279: tap0, 1280..2559: tap1
__device__ __align__(256) __nv_bfloat16 g_Blo[2 * C * C];

// ---------------- helpers ----------------
__device__ __forceinline__ uint32_t smem_u32(const void* p) {
    uint32_t a;
    asm("{ .reg .u64 t; cvta.to.shared.u64 t, %1; cvt.u32.u64 %0, t; }" : "=r"(a) : "l"(p));
    return a;
}
// 64B rows, swizzle XORs (row/2)&7 into the 16B-unit bits -> conflict-free ldmatrix
__device__ __forceinline__ uint32_t swz(uint32_t o) { return o ^ (((o >> 7) & 7u) << 4); }

__device__ __forceinline__ void cp16(uint32_t dst, const void* src) {
    asm volatile("cp.async.cg.shared.global [%0], [%1], 16;" :: "r"(dst), "l"(src) : "memory");
}
#define CP_COMMIT() asm volatile("cp.async.commit_group;" ::: "memory")

__device__ __forceinline__ void ldm_x4(uint32_t* r, uint32_t addr) {
    asm volatile("ldmatrix.sync.aligned.m8n8.x4.shared.b16 {%0,%1,%2,%3}, [%4];"
                 : "=r"(r[0]), "=r"(r[1]), "=r"(r[2]), "=r"(r[3]) : "r"(addr));
}
__device__ __forceinline__ void mma_bf16(float* c, const uint32_t* a, uint32_t b0, uint32_t b1) {
    asm volatile(
        "mma.sync.aligned.m16n8k16.row.col.f32.bf16.bf16.f32 "
        "{%0,%1,%2,%3}, {%4,%5,%6,%7}, {%8,%9}, {%0,%1,%2,%3};"
        : "+f"(c[0]), "+f"(c[1]), "+f"(c[2]), "+f"(c[3])
        : "r"(a[0]), "r"(a[1]), "r"(a[2]), "r"(a[3]), "r"(b0), "r"(b1));
}

// ---------------- prep: split fp32 -> bf16 hi/lo ----------------
__global__ __launch_bounds__(256)
void prep_kernel(const float* __restrict__ X, const float* __restrict__ Wc) {
    int i = blockIdx.x * 256 + threadIdx.x;
    if (i < NIMG * C) {
        float v = X[i];
        __nv_bfloat16 h = __float2bfloat16(v);
        g_Xhi[i] = h;
        g_Xlo[i] = __float2bfloat16(v - __bfloat162float(h));
    }
    if (i < 2 * C * C) {
        int n = i / C, k = i % C;
        int o = (n < C) ? n : (n - C);
        int tap = (n < C) ? 0 : 1;
        float v = Wc[((size_t)o * C + k) * 2 + tap];
        __nv_bfloat16 h = __float2bfloat16(v);
        g_Bhi[i] = h;
        g_Blo[i] = __float2bfloat16(v - __bfloat162float(h));
    }
}

// ---------------- bf16 mma.sync GEMM: Y[8192,2560] = Xsplit @ Bsplit^T ----------------
__global__ __launch_bounds__(256, 2)
void gemm_mma_kernel() {
    extern __shared__ char dsm[];
    const uint32_t sbase = smem_u32(dsm);

    const int tid  = threadIdx.x;
    const int lane = tid & 31;
    const int wrp  = tid >> 5;
    const int wm   = wrp & 1;        // 2 warps along M
    const int wn   = wrp >> 1;       // 4 warps along N
    const int bm   = blockIdx.y * TMt;
    const int bn   = blockIdx.x * TNt;

    // Lane-invariant swizzled offsets.
    // swz flips bits 4-6 from bits 7-9; mt*1024 / p*1024 additions never touch
    // bits 4-9 (carry stays >=10), but the ks*32 term (bit 5) must be XORed,
    // not added, because swz(base) may already have bit 5 set.
    const int rowA  = wm * 64 + ((lane >> 3) & 1) * 8 + (lane & 7);
    const int unitA = (lane >> 4) & 1;
    const uint32_t aOff = swz((uint32_t)(rowA * 64 + unitA * 16));
    const int rowB  = wn * 32 + ((lane >> 4) & 1) * 8 + (lane & 7);
    const int unitB = (lane >> 3) & 1;
    const uint32_t bOff = 8192u + swz((uint32_t)(rowB * 64 + unitB * 16));

    float acc[4][4][4];
#pragma unroll
    for (int i = 0; i < 4; i++)
#pragma unroll
        for (int j = 0; j < 4; j++)
#pragma unroll
            for (int k = 0; k < 4; k++) acc[i][j][k] = 0.f;

    const __nv_bfloat16* Apl[3] = {g_Xhi, g_Xhi, g_Xlo};
    const __nv_bfloat16* Bpl[3] = {g_Bhi, g_Blo, g_Bhi};

    auto load_chunk = [&](int kidx, int stage) {
        const int plane = kidx / 40;
        const int k0 = (kidx % 40) * KCH;
        const __nv_bfloat16* Ap = Apl[plane];
        const __nv_bfloat16* Bp = Bpl[plane];
        const uint32_t aB = sbase + stage * STAGE_BYTES;
        const uint32_t bB = aB + 8192;
#pragma unroll
        for (int i = 0; i < 2; i++) {
            int idx = tid + i * 256;
            int row = idx >> 2, u = idx & 3;
            cp16(aB + swz((uint32_t)(row * 64 + u * 16)),
                 Ap + (size_t)(bm + row) * C + k0 + u * 8);
        }
#pragma unroll
        for (int i = 0; i < 2; i++) {
            int idx = tid + i * 256;
            int row = idx >> 2, u = idx & 3;
            cp16(bB + swz((uint32_t)(row * 64 + u * 16)),
                 Bp + (size_t)(bn + row) * C + k0 + u * 8);
        }
        CP_COMMIT();
    };

    // prologue: stages 0..2
    load_chunk(0, 0); load_chunk(1, 1); load_chunk(2, 2);

    for (int i = 0; i < NCHUNK; i++) {
        asm volatile("cp.async.wait_group 2;" ::: "memory");
        __syncthreads();

        // issue next loads early (stage reused from iter i-1, safe after sync)
        if (i + 3 < NCHUNK) load_chunk(i + 3, (i + 3) & 3);
        else CP_COMMIT();   // keep group count uniform

        const uint32_t stA = sbase + (i & 3) * STAGE_BYTES;
#pragma unroll
        for (int ks = 0; ks < 2; ks++) {
            uint32_t aF[4][4], bF[2][4];
#pragma unroll
            for (int mt = 0; mt < 4; mt++)
                ldm_x4(aF[mt], ((stA + aOff + mt * 1024) ^ (ks * 32)));
#pragma unroll
            for (int p = 0; p < 2; p++)
                ldm_x4(bF[p], ((stA + bOff + p * 1024) ^ (ks * 32)));
#pragma unroll
            for (int mt = 0; mt < 4; mt++)
#pragma unroll
                for (int nt = 0; nt < 4; nt++)
                    mma_bf16(acc[mt][nt], aF[mt], bF[nt >> 1][(nt & 1) * 2],
                             bF[nt >> 1][(nt & 1) * 2 + 1]);
        }
    }

    // epilogue: direct fp32 stores (float2 per fragment row)
    const bool plane1 = (bn >= C);
    float* Yp = plane1 ? g_Y1 : g_Y0;
    const int bn_loc = plane1 ? (bn - C) : bn;
    const int r0 = bm + wm * 64 + (lane >> 2);
    const int cbase = bn_loc + wn * 32 + (lane & 3) * 2;
#pragma unroll
    for (int mt = 0; mt < 4; mt++) {
#pragma unroll
        for (int nt = 0; nt < 4; nt++) {
            const int col = cbase + nt * 8;
            *(float2*)&Yp[(size_t)(r0 + mt * 16) * C + col] =
                make_float2(acc[mt][nt][0], acc[mt][nt][1]);
            *(float2*)&Yp[(size_t)(r0 + mt * 16 + 8) * C + col] =
                make_float2(acc[mt][nt][2], acc[mt][nt][3]);
        }
    }
}

// ---------------- Threefry-2x32, JAX *partitionable* stream ----------------
__device__ __forceinline__ uint32_t rotl32(uint32_t x, int r) {
    return __funnelshift_l(x, x, r);
}

__device__ __forceinline__ int tf_n1(uint32_t base) {
    const uint32_t ks0 = 0u, ks1 = 42u, ks2 = 0x1BD11BF0u;
    uint32_t x0[5], x1[5];
#pragma unroll
    for (int d = 0; d < 5; d++) {
        x0[d] = ks0;
        x1[d] = base + (uint32_t)d * PC + ks1;
    }
#define TF_ROUND(r)                                           \
    {                                                         \
        _Pragma("unroll") for (int e = 0; e < 5; e++) {       \
            x0[e] += x1[e];                                   \
            x1[e] = rotl32(x1[e], (r));                       \
            x1[e] ^= x0[e];                                   \
        }                                                     \
    }
#define TF_INJ(a, b)                                          \
    {                                                         \
        _Pragma("unroll") for (int e = 0; e < 5; e++) {       \
            x0[e] += (a); x1[e] += (b);                       \
        }                                                     \
    }
    TF_ROUND(13) TF_ROUND(15) TF_ROUND(26) TF_ROUND(6)  TF_INJ(ks1, ks2 + 1u)
    TF_ROUND(17) TF_ROUND(29) TF_ROUND(16) TF_ROUND(24) TF_INJ(ks2, ks0 + 2u)
    TF_ROUND(13) TF_ROUND(15) TF_ROUND(26) TF_ROUND(6)  TF_INJ(ks0, ks1 + 3u)
    TF_ROUND(17) TF_ROUND(29) TF_ROUND(16) TF_ROUND(24) TF_INJ(ks1, ks2 + 4u)
    TF_ROUND(13) TF_ROUND(15) TF_ROUND(26) TF_ROUND(6)  TF_INJ(ks2, ks0 + 5u)
#undef TF_ROUND
#undef TF_INJ
    int msum = 0;
#pragma unroll
    for (int d = 0; d < 5; d++) msum += (int)((x0[d] ^ x1[d]) >> 31);
    return 5 - msum;
}

// ---------------- Kernel B: relu + mask-count + 3 heads + segment mean ----
__global__ __launch_bounds__(256, 4)
void reduce_kernel(const float* __restrict__ bc,
                   const float* __restrict__ W0, const float* __restrict__ b0,
                   const float* __restrict__ W1, const float* __restrict__ b1,
                   const float* __restrict__ W2, const float* __restrict__ b2,
                   float* __restrict__ out) {
    __shared__ float sW0[C], sW1[C], sW2[C], sbc[C];
    __shared__ float red[24];

    const int tid = threadIdx.x;
    for (int i = tid; i < C; i += 256) {
        sW0[i] = W0[i]; sW1[i] = W1[i]; sW2[i] = W2[i]; sbc[i] = bc[i];
    }
    __syncthreads();

    const int b = blockIdx.x;

    float a0 = 0.f, a1 = 0.f, a2 = 0.f;

#pragma unroll
    for (int j = 0; j < PAIRS; j++) {
        const int ii = (j < 3) ? 0 : ((j < 5) ? 1 : 2);
        const int jj = (j < 3) ? (j + 1) : ((j < 5) ? (j - 1) : 3);
        const float* y0 = g_Y0 + (size_t)(4 * b + ii) * C;
        const float* y1 = g_Y1 + (size_t)(4 * b + jj) * C;
        const uint32_t p = (uint32_t)(PAIRS * b + j);

        for (int c = tid; c < C; c += 256) {
            float xc = fmaxf(y0[c] + y1[c] + sbc[c], 0.f);
            const int n1 = tf_n1(p * 1280u + (uint32_t)c);
            float t = xc * (float)n1;
            a0 = fmaf(t, sW0[c], a0);
            a1 = fmaf(t, sW1[c], a1);
            a2 = fmaf(t, sW2[c], a2);
        }
    }

    float vals[3] = {a0, a1, a2};
    const int lane = tid & 31, wid = tid >> 5;
#pragma unroll
    for (int v = 0; v < 3; v++) {
        float s = vals[v];
#pragma unroll
        for (int off = 16; off; off >>= 1) s += __shfl_down_sync(0xffffffffu, s, off);
        if (lane == 0) red[v * 8 + wid] = s;
    }
    __syncthreads();
    if (tid < 3) {
        float s = 0.f;
#pragma unroll
        for (int w = 0; w < 8; w++) s += red[tid * 8 + w];
        const float* bias = (tid == 0) ? b0 : ((tid == 1) ? b1 : b2);
        out[b * 3 + tid] = bias[0] + s * (1.0f / 15.0f);
    }
}

extern "C" void kernel_launch(void* const* d_in, const int* in_sizes, int n_in,
                              void* d_out, int out_size) {
    (void)in_sizes; (void)n_in; (void)out_size;
    const float* x  = (const float*)d_in[0];
    // d_in[1] = ids2 (static structure) — unused
    const float* Wc = (const float*)d_in[2];
    const float* bc = (const float*)d_in[3];
    const float* W0 = (const float*)d_in[4];
    const float* b0 = (const float*)d_in[5];
    const float* W1 = (const float*)d_in[6];
    const float* b1 = (const float*)d_in[7];
    const float* W2 = (const float*)d_in[8];
    const float* b2 = (const float*)d_in[9];
    float* out = (float*)d_out;

    cudaFuncSetAttribute(gemm_mma_kernel, cudaFuncAttributeMaxDynamicSharedMemorySize,
                         DYN_SMEM);

    prep_kernel<<<(NIMG * C + 255) / 256, 256>>>(x, Wc);
    dim3 gridG(2 * C / TNt, NIMG / TMt);   // (20, 64)
    gemm_mma_kernel<<<gridG, 256, DYN_SMEM>>>();
    reduce_kernel<<<NPAT, 256>>>(bc, W0, b0, W1, b1, W2, b2, out);
}